// round 6
// baseline (speedup 1.0000x reference)
#include <cuda_runtime.h>
#include <cstdint>
#include <cstddef>

#define N0  2048
#define NN1 3072
#define DM  1024
#define NH  16
#define DKH 64

// ---------------- scratch (device globals; no allocation) ----------------
__device__ float g_Q [(size_t)N0 * DM];
__device__ float g_K [(size_t)N0 * DM];
__device__ float g_V [(size_t)N0 * DM];
__device__ float g_Q1[(size_t)NN1 * DM];
__device__ float g_K1[(size_t)NN1 * DM];
__device__ float g_V1[(size_t)NN1 * DM];
__device__ float g_C [(size_t)NN1 * DM];        // dir1 context, [H][DK][N1] flat
__device__ float g_C1[(size_t)N0 * DM];         // dir2 context, [H][DK][N0] flat

// --------------------------- tf32 helpers --------------------------------
__device__ __forceinline__ uint32_t f2t(float f) {
    uint32_t r;
    asm("cvt.rna.tf32.f32 %0, %1;" : "=r"(r) : "f"(f));
    return r;
}

__device__ __forceinline__ void mma8(float c[4], const uint32_t a[4], const uint32_t b[2]) {
    asm volatile(
        "mma.sync.aligned.m16n8k8.row.col.f32.tf32.tf32.f32 "
        "{%0,%1,%2,%3}, {%4,%5,%6,%7}, {%8,%9}, {%0,%1,%2,%3};"
        : "+f"(c[0]), "+f"(c[1]), "+f"(c[2]), "+f"(c[3])
        : "r"(a[0]), "r"(a[1]), "r"(a[2]), "r"(a[3]), "r"(b[0]), "r"(b[1]));
}

// ============ batched NN GEMM (tf32, frag-packed A, ping-pong) ============
// Up to 6 independent GEMMs (same N=K=1024) selected by blockIdx.z.
// 128x128 tile, BK=32, 8 warps (2m x 4n), warp tile 64x32.
//
// A tile lives in smem in FRAGMENT-PACKED layout: for block index
// Ablk = (mw2*4+ks)*4+mi (mw2: m-half, ks: k-step of 8, mi: 16-row sub),
// thread `lane`'s 4 A-frag words are the uint4 at word address
//   Ablk*128 + ((lane ^ (Ablk&7)) << 2)
// Store side (scalar, verified conflict-free): element A[m][k] with
// m = mw2*64+mi*16+r8*8+g, k = ks*8+hi*4+t goes to
//   Ablk*128 + (((g*4+t) ^ ((ks&1)*4+mi)) << 2) + (r8 + 2*hi)
struct GN {
    const float* A[6];
    const float* B[6];
    float*       C[6];
    int          M[6];
};

#define BPAD 132
#define A_WORDS (32 * 128)                         // 4096
#define GEMM_BUF_WORDS (A_WORDS + 32 * BPAD)       // 8320 words / buffer
#define GEMM_SMEM_BYTES (2 * GEMM_BUF_WORDS * 4)   // 66560 B

// decode v (0..1023) -> (m, kc) for the frag-packed A gmem load mapping
__device__ __forceinline__ void a_decode(int v, int& m, int& kc,
                                         int& Ablk, int& sig, int& g, int& w)
{
    int r8 = v & 1, hi = (v >> 1) & 1, mi = (v >> 2) & 3, gp = (v >> 4) & 1;
    int u = v >> 5;
    int g12 = u & 3, ks = (u >> 2) & 3, mw2 = u >> 4;
    g = g12 * 2 + gp;
    m = mw2 * 64 + mi * 16 + r8 * 8 + g;
    kc = ks * 8 + hi * 4;
    Ablk = (mw2 * 4 + ks) * 4 + mi;
    sig = (ks & 1) * 4 + mi;
    w = r8 + 2 * hi;
}

__device__ __forceinline__ void stage_tiles(uint32_t* As, uint32_t* Bs,
                                            const float4 ra[4], const float4 rb[4],
                                            int tid)
{
    #pragma unroll
    for (int p = 0; p < 4; p++) {
        int v = tid + p * 256;
        int m, kc, Ablk, sig, g, w;
        a_decode(v, m, kc, Ablk, sig, g, w);
        const float* f = (const float*)&ra[p];
        uint32_t* base = &As[Ablk * 128 + w];
        #pragma unroll
        for (int e = 0; e < 4; e++)
            base[((g * 4 + e) ^ sig) << 2] = f2t(f[e]);

        int kr = v >> 5, nc = (v & 31) * 4;
        uint32_t* eb = &Bs[kr * BPAD + nc];
        eb[0] = f2t(rb[p].x); eb[1] = f2t(rb[p].y);
        eb[2] = f2t(rb[p].z); eb[3] = f2t(rb[p].w);
    }
}

__global__ void __launch_bounds__(256, 2) gemmN_tf32(GN p, int N, int K)
{
    extern __shared__ uint32_t smU[];

    const int z = blockIdx.z;
    const float* __restrict__ A = p.A[z];
    const float* __restrict__ B = p.B[z];
    float* __restrict__ C = p.C[z];
    const int M = p.M[z];

    const int bm = blockIdx.y * 128;
    if (bm >= M) return;
    const int bn = blockIdx.x * 128;

    const int tid = threadIdx.x;
    const int wid = tid >> 5, lane = tid & 31;
    const int g = lane >> 2, t = lane & 3;
    const int mw2 = wid >> 2, nW = (wid & 3) * 32;

    float acc[4][4][4] = {};
    float4 ra[4], rb[4];

    // prologue: load tile 0
    #pragma unroll
    for (int pp = 0; pp < 4; pp++) {
        int v = tid + pp * 256;
        int m, kc, Ablk, sig, gg, w;
        a_decode(v, m, kc, Ablk, sig, gg, w);
        ra[pp] = *(const float4*)&A[(size_t)(bm + m) * K + kc];
        int kr = v >> 5, nc = (v & 31) * 4;
        rb[pp] = *(const float4*)&B[(size_t)kr * N + bn + nc];
    }
    stage_tiles(smU, smU + A_WORDS, ra, rb, tid);
    __syncthreads();

    int buf = 0;
    for (int k0 = 0; k0 < K; k0 += 32) {
        const bool more = (k0 + 32 < K);
        if (more) {
            #pragma unroll
            for (int pp = 0; pp < 4; pp++) {
                int v = tid + pp * 256;
                int m, kc, Ablk, sig, gg, w;
                a_decode(v, m, kc, Ablk, sig, gg, w);
                ra[pp] = *(const float4*)&A[(size_t)(bm + m) * K + k0 + 32 + kc];
                int kr = v >> 5, nc = (v & 31) * 4;
                rb[pp] = *(const float4*)&B[(size_t)(k0 + 32 + kr) * N + bn + nc];
            }
        }

        const uint32_t* As = smU + buf * GEMM_BUF_WORDS;
        const uint32_t* Bs = As + A_WORDS;

        #pragma unroll
        for (int ks = 0; ks < 4; ks++) {
            uint32_t af[4][4], bf[4][2];
            #pragma unroll
            for (int mi = 0; mi < 4; mi++) {
                int Ablk = (mw2 * 4 + ks) * 4 + mi;
                const uint4 u4 = *(const uint4*)&As[Ablk * 128 + ((lane ^ (Ablk & 7)) << 2)];
                af[mi][0] = u4.x; af[mi][1] = u4.y; af[mi][2] = u4.z; af[mi][3] = u4.w;
            }
            const int ks8 = ks * 8;
            #pragma unroll
            for (int ni = 0; ni < 4; ni++) {
                int c = nW + ni * 8 + g;
                bf[ni][0] = Bs[(ks8 + t) * BPAD + c];
                bf[ni][1] = Bs[(ks8 + t + 4) * BPAD + c];
            }
            #pragma unroll
            for (int mi = 0; mi < 4; mi++)
                #pragma unroll
                for (int ni = 0; ni < 4; ni++)
                    mma8(acc[mi][ni], af[mi], bf[ni]);
        }

        if (more)
            stage_tiles(smU + (buf ^ 1) * GEMM_BUF_WORDS,
                        smU + (buf ^ 1) * GEMM_BUF_WORDS + A_WORDS, ra, rb, tid);
        __syncthreads();
        buf ^= 1;
    }

    const int mW = mw2 * 64;
    #pragma unroll
    for (int mi = 0; mi < 4; mi++)
        #pragma unroll
        for (int ni = 0; ni < 4; ni++) {
            int r = bm + mW + mi * 16 + g;
            int c = bn + nW + ni * 8 + 2 * t;
            *(float2*)&C[(size_t)r * N + c] =
                make_float2(acc[mi][ni][0], acc[mi][ni][1]);
            *(float2*)&C[(size_t)(r + 8) * N + c] =
                make_float2(acc[mi][ni][2], acc[mi][ni][3]);
        }
}

// ======================= fused flash cross-attention v2 ===================
#define KP  68
#define VP  72
#define CPW 132
#define FLASH_SMEM_WORDS (64 * KP + 64 * VP)   // 8960 words
#define QSC 0.18033688011112042f               // 0.125 * log2(e)

struct FA {
    const float* Q; const float* K; const float* V;
    float* Ct; int Nq; int Nk;
};

__global__ void __launch_bounds__(128, 2) flash2(FA a0, FA a1, int nbq0)
{
    __shared__ uint32_t sm[FLASH_SMEM_WORDS];
    uint32_t* Ks = sm;                  // 64 x KP
    uint32_t* Vs = sm + 64 * KP;        // 64 x VP

    const bool d1 = (blockIdx.x < nbq0);
    const FA a = d1 ? a0 : a1;
    const int bq = (d1 ? blockIdx.x : blockIdx.x - nbq0) * 128;
    const int h = blockIdx.y;
    const int Nq = a.Nq, Nk = a.Nk;
    const float* __restrict__ Qg = a.Q;
    const float* __restrict__ Kg = a.K;
    const float* __restrict__ Vg = a.V;

    const int tid = threadIdx.x;
    const int wid = tid >> 5, lane = tid & 31;
    const int g = lane >> 2, t = lane & 3;
    const int qw = wid * 32;

    #pragma unroll
    for (int pp = 0; pp < 16; pp++) {
        int idx = tid + pp * 128;
        int r = idx >> 4, c4 = (idx & 15) << 2;
        float4 q = *(const float4*)&Qg[(size_t)(bq + r) * DM + h * DKH + c4];
        uint4 u;
        u.x = f2t(q.x * QSC); u.y = f2t(q.y * QSC);
        u.z = f2t(q.z * QSC); u.w = f2t(q.w * QSC);
        *(uint4*)&sm[r * KP + c4] = u;
    }
    __syncthreads();

    uint32_t aq[2][8][4];
    #pragma unroll
    for (int grp = 0; grp < 2; grp++)
        #pragma unroll
        for (int ks = 0; ks < 8; ks++) {
            int r0 = qw + grp * 16 + g;
            aq[grp][ks][0] = sm[r0 * KP + ks * 8 + t];
            aq[grp][ks][1] = sm[(r0 + 8) * KP + ks * 8 + t];
            aq[grp][ks][2] = sm[r0 * KP + ks * 8 + t + 4];
            aq[grp][ks][3] = sm[(r0 + 8) * KP + ks * 8 + t + 4];
        }
    __syncthreads();

    float m[2][2], l[2][2];
    #pragma unroll
    for (int i = 0; i < 2; i++) { m[i][0] = m[i][1] = -1e30f; l[i][0] = l[i][1] = 0.f; }
    float o[2][8][4] = {};

    for (int kt = 0; kt < Nk; kt += 64) {
        #pragma unroll
        for (int pp = 0; pp < 8; pp++) {
            int idx = tid + pp * 128;
            int r = idx >> 4, c4 = (idx & 15) << 2;
            float4 kv = *(const float4*)&Kg[(size_t)(kt + r) * DM + h * DKH + c4];
            uint4 uk;
            uk.x = f2t(kv.x); uk.y = f2t(kv.y); uk.z = f2t(kv.z); uk.w = f2t(kv.w);
            *(uint4*)&Ks[r * KP + c4] = uk;
            float4 vv = *(const float4*)&Vg[(size_t)(kt + r) * DM + h * DKH + c4];
            int pr = (r & 0x38) | ((r & 7) >> 1) | ((r & 1) << 2);
            uint4 uv;
            uv.x = f2t(vv.x); uv.y = f2t(vv.y); uv.z = f2t(vv.z); uv.w = f2t(vv.w);
            *(uint4*)&Vs[pr * VP + c4] = uv;
        }
        __syncthreads();

        float s[2][8][4] = {};
        #pragma unroll
        for (int ni = 0; ni < 8; ni++) {
            #pragma unroll
            for (int ks = 0; ks < 8; ks++) {
                uint32_t bf[2];
                bf[0] = Ks[(ni * 8 + g) * KP + ks * 8 + t];
                bf[1] = Ks[(ni * 8 + g) * KP + ks * 8 + t + 4];
                mma8(s[0][ni], aq[0][ks], bf);
                mma8(s[1][ni], aq[1][ks], bf);
            }
        }

        #pragma unroll
        for (int grp = 0; grp < 2; grp++) {
            float mx0 = -1e30f, mx1 = -1e30f;
            #pragma unroll
            for (int ni = 0; ni < 8; ni++) {
                mx0 = fmaxf(mx0, fmaxf(s[grp][ni][0], s[grp][ni][1]));
                mx1 = fmaxf(mx1, fmaxf(s[grp][ni][2], s[grp][ni][3]));
            }
            #pragma unroll
            for (int off = 1; off <= 2; off <<= 1) {
                mx0 = fmaxf(mx0, __shfl_xor_sync(0xffffffffu, mx0, off));
                mx1 = fmaxf(mx1, __shfl_xor_sync(0xffffffffu, mx1, off));
            }
            float mn0 = fmaxf(m[grp][0], mx0), mn1 = fmaxf(m[grp][1], mx1);
            float cr0 = exp2f(m[grp][0] - mn0), cr1 = exp2f(m[grp][1] - mn1);
            m[grp][0] = mn0; m[grp][1] = mn1;

            float rs0 = 0.f, rs1 = 0.f;
            #pragma unroll
            for (int ni = 0; ni < 8; ni++) {
                s[grp][ni][0] = exp2f(s[grp][ni][0] - mn0);
                s[grp][ni][1] = exp2f(s[grp][ni][1] - mn0);
                s[grp][ni][2] = exp2f(s[grp][ni][2] - mn1);
                s[grp][ni][3] = exp2f(s[grp][ni][3] - mn1);
                rs0 += s[grp][ni][0] + s[grp][ni][1];
                rs1 += s[grp][ni][2] + s[grp][ni][3];
            }
            #pragma unroll
            for (int off = 1; off <= 2; off <<= 1) {
                rs0 += __shfl_xor_sync(0xffffffffu, rs0, off);
                rs1 += __shfl_xor_sync(0xffffffffu, rs1, off);
            }
            l[grp][0] = l[grp][0] * cr0 + rs0;
            l[grp][1] = l[grp][1] * cr1 + rs1;
            #pragma unroll
            for (int dn = 0; dn < 8; dn++) {
                o[grp][dn][0] *= cr0; o[grp][dn][1] *= cr0;
                o[grp][dn][2] *= cr1; o[grp][dn][3] *= cr1;
            }
        }

        #pragma unroll
        for (int kk = 0; kk < 8; kk++) {
            uint32_t ap0[4], ap1[4];
            ap0[0] = f2t(s[0][kk][0]); ap0[1] = f2t(s[0][kk][2]);
            ap0[2] = f2t(s[0][kk][1]); ap0[3] = f2t(s[0][kk][3]);
            ap1[0] = f2t(s[1][kk][0]); ap1[1] = f2t(s[1][kk][2]);
            ap1[2] = f2t(s[1][kk][1]); ap1[3] = f2t(s[1][kk][3]);
            #pragma unroll
            for (int dn = 0; dn < 8; dn++) {
                uint32_t bf[2];
                bf[0] = Vs[(kk * 8 + t) * VP + dn * 8 + g];
                bf[1] = Vs[(kk * 8 + t + 4) * VP + dn * 8 + g];
                mma8(o[0][dn], ap0, bf);
                mma8(o[1][dn], ap1, bf);
            }
        }
        __syncthreads();
    }

    float* Cs = (float*)sm;             // 64 x CPW
    #pragma unroll
    for (int grp = 0; grp < 2; grp++) {
        float i0 = 1.0f / l[grp][0], i1 = 1.0f / l[grp][1];
        int q = qw + grp * 16 + g;
        #pragma unroll
        for (int dn = 0; dn < 8; dn++) {
            int d = dn * 8 + 2 * t;
            Cs[d * CPW + q]           = o[grp][dn][0] * i0;
            Cs[(d + 1) * CPW + q]     = o[grp][dn][1] * i0;
            Cs[d * CPW + q + 8]       = o[grp][dn][2] * i1;
            Cs[(d + 1) * CPW + q + 8] = o[grp][dn][3] * i1;
        }
    }
    __syncthreads();

    float* Ct = a.Ct;
    #pragma unroll
    for (int pp = 0; pp < 16; pp++) {
        int idx = tid + pp * 128;
        int d = idx >> 5, q4 = (idx & 31) * 4;
        *(float4*)&Ct[(size_t)(h * DKH + d) * Nq + bq + q4] = *(float4*)&Cs[d * CPW + q4];
    }
}

// --------------------------------- launch ---------------------------------
extern "C" void kernel_launch(void* const* d_in, const int* in_sizes, int n_in,
                              void* d_out, int out_size)
{
    const float* X    = (const float*)d_in[0];
    const float* X1   = (const float*)d_in[1];
    const float* WQ   = (const float*)d_in[2];
    const float* WK   = (const float*)d_in[3];
    const float* WV   = (const float*)d_in[4];
    const float* WQ1  = (const float*)d_in[5];
    const float* WK1  = (const float*)d_in[6];
    const float* WV1  = (const float*)d_in[7];
    const float* Wfc  = (const float*)d_in[8];
    const float* Wfc1 = (const float*)d_in[9];
    float* out = (float*)d_out;

    float *Q, *K, *V, *Q1, *K1, *V1, *C, *C1;
    cudaGetSymbolAddress((void**)&Q,  g_Q);
    cudaGetSymbolAddress((void**)&K,  g_K);
    cudaGetSymbolAddress((void**)&V,  g_V);
    cudaGetSymbolAddress((void**)&Q1, g_Q1);
    cudaGetSymbolAddress((void**)&K1, g_K1);
    cudaGetSymbolAddress((void**)&V1, g_V1);
    cudaGetSymbolAddress((void**)&C,  g_C);
    cudaGetSymbolAddress((void**)&C1, g_C1);

    static bool attr_done = false;
    if (!attr_done) {
        cudaFuncSetAttribute(gemmN_tf32,
            cudaFuncAttributeMaxDynamicSharedMemorySize, GEMM_SMEM_BYTES);
        attr_done = true;
    }

    const dim3 blk(256);

    // ALL SIX QKV projections in one launch (z selects GEMM)
    {
        GN p;
        p.A[0] = X;   p.A[1] = X;   p.A[2] = X;
        p.A[3] = X1;  p.A[4] = X1;  p.A[5] = X1;
        p.B[0] = WQ;  p.B[1] = WK;  p.B[2] = WV;
        p.B[3] = WQ1; p.B[4] = WK1; p.B[5] = WV1;
        p.C[0] = Q;   p.C[1] = K;   p.C[2] = V;
        p.C[3] = Q1;  p.C[4] = K1;  p.C[5] = V1;
        p.M[0] = N0;  p.M[1] = N0;  p.M[2] = N0;
        p.M[3] = NN1; p.M[4] = NN1; p.M[5] = NN1;
        gemmN_tf32<<<dim3(DM / 128, NN1 / 128, 6), blk, GEMM_SMEM_BYTES>>>(p, DM, DM);
    }

    // fused attention: both directions in ONE launch
    {
        FA a0, a1;
        a0.Q = Q1; a0.K = K;  a0.V = V;  a0.Ct = C;  a0.Nq = NN1; a0.Nk = N0;
        a1.Q = Q;  a1.K = K1; a1.V = V1; a1.Ct = C1; a1.Nq = N0;  a1.Nk = NN1;
        const int nbq0 = NN1 / 128;                  // 24
        const int nbq1 = N0 / 128;                   // 16
        flash2<<<dim3(nbq0 + nbq1, NH), dim3(128)>>>(a0, a1, nbq0);
    }

    // final FCs in one launch
    {
        GN p;
        p.A[0] = C;    p.A[1] = C1;
        p.B[0] = Wfc;  p.B[1] = Wfc1;
        p.C[0] = out;  p.C[1] = out + (size_t)NN1 * DM;
        p.M[0] = NN1;  p.M[1] = N0;
        p.A[2] = p.A[3] = p.A[4] = p.A[5] = C;
        p.B[2] = p.B[3] = p.B[4] = p.B[5] = Wfc;
        p.C[2] = p.C[3] = p.C[4] = p.C[5] = out;
        p.M[2] = p.M[3] = p.M[4] = p.M[5] = 0;
        gemmN_tf32<<<dim3(DM / 128, NN1 / 128, 2), blk, GEMM_SMEM_BYTES>>>(p, DM, DM);
    }
}

// round 7
// speedup vs baseline: 1.1892x; 1.1892x over previous
#include <cuda_runtime.h>
#include <cstdint>
#include <cstddef>

#define N0  2048
#define NN1 3072
#define DM  1024
#define NH  16
#define DKH 64
#define MEG 1048576

// ---------------- scratch (device globals; no allocation) ----------------
__device__ float g_Q [(size_t)N0 * DM];
__device__ float g_K [(size_t)N0 * DM];
__device__ float g_V [(size_t)N0 * DM];
__device__ float g_Q1[(size_t)NN1 * DM];
__device__ float g_K1[(size_t)NN1 * DM];
__device__ float g_V1[(size_t)NN1 * DM];
__device__ float g_C [(size_t)NN1 * DM];        // dir1 context, [H][DK][N1] flat (tf32-valued)
__device__ float g_C1[(size_t)N0 * DM];         // dir2 context, [H][DK][N0] flat (tf32-valued)
__device__ float g_cv[(size_t)13 * MEG];        // tf32-rounded copies of X,X1,W*

// --------------------------- tf32 helpers --------------------------------
__device__ __forceinline__ uint32_t f2t(float f) {
    uint32_t r;
    asm("cvt.rna.tf32.f32 %0, %1;" : "=r"(r) : "f"(f));
    return r;
}

__device__ __forceinline__ void mma8(float c[4], const uint32_t a[4], const uint32_t b[2]) {
    asm volatile(
        "mma.sync.aligned.m16n8k8.row.col.f32.tf32.tf32.f32 "
        "{%0,%1,%2,%3}, {%4,%5,%6,%7}, {%8,%9}, {%0,%1,%2,%3};"
        : "+f"(c[0]), "+f"(c[1]), "+f"(c[2]), "+f"(c[3])
        : "r"(a[0]), "r"(a[1]), "r"(a[2]), "r"(a[3]), "r"(b[0]), "r"(b[1]));
}

__device__ __forceinline__ uint32_t smem_u32(const void* p) {
    uint32_t a;
    asm("{ .reg .u64 tmp; cvta.to.shared.u64 tmp, %1; cvt.u32.u64 %0, tmp; }"
        : "=r"(a) : "l"(p));
    return a;
}

__device__ __forceinline__ void cpa16(uint32_t s, const void* g) {
    asm volatile("cp.async.cg.shared.global [%0], [%1], 16;" :: "r"(s), "l"(g));
}

// ================= pre-pass: round arrays to tf32-valued fp32 =============
struct CV {
    const float4* src[10];
    float4*       dst[10];
    int           n4[10];
};

__global__ void __launch_bounds__(256) cvt_tf32(CV cv)
{
    const int z = blockIdx.z;
    const float4* __restrict__ s = cv.src[z];
    float4* __restrict__ d = cv.dst[z];
    const int n = cv.n4[z];
    for (int i = blockIdx.x * blockDim.x + threadIdx.x; i < n;
         i += gridDim.x * blockDim.x) {
        float4 v = s[i];
        v.x = __uint_as_float(f2t(v.x));
        v.y = __uint_as_float(f2t(v.y));
        v.z = __uint_as_float(f2t(v.z));
        v.w = __uint_as_float(f2t(v.w));
        d[i] = v;
    }
}

// ====== batched NN GEMM: tf32-valued inputs, cp.async, 64x64 warp tiles ===
// Up to 6 GEMMs (N=K=1024) via blockIdx.z. CTA 128x128, 128 threads,
// 4 warps (2x2), warp tile 64x64, BK=32, 2-stage cp.async pipeline.
struct GN {
    const float* A[6];
    const float* B[6];
    float*       C[6];
    int          M[6];
};

#define APAD 36
#define BPAD 136
#define A_WORDS (128 * APAD)                       // 4608
#define B_WORDS (32 * BPAD)                        // 4352
#define GEMM_BUF_WORDS (A_WORDS + B_WORDS)         // 8960
#define GEMM_SMEM_BYTES (2 * GEMM_BUF_WORDS * 4)   // 71680

__global__ void __launch_bounds__(128, 2) gemmN_tf32(GN p, int N, int K)
{
    extern __shared__ uint32_t smU[];
    const uint32_t smb = smem_u32(smU);

    const int z = blockIdx.z;
    const float* __restrict__ A = p.A[z];
    const float* __restrict__ B = p.B[z];
    float* __restrict__ C = p.C[z];
    const int M = p.M[z];

    const int bm = blockIdx.y * 128;
    if (bm >= M) return;
    const int bn = blockIdx.x * 128;

    const int tid = threadIdx.x;
    const int wid = tid >> 5, lane = tid & 31;
    const int g = lane >> 2, t = lane & 3;
    const int mW = (wid >> 1) * 64, nW = (wid & 1) * 64;

    // per-thread copy map (8 A-chunks + 8 B-chunks of 16B per stage)
    // A chunk: v = tid + p*128 -> row m=v>>3, col kc=(v&7)*4
    // B chunk: row kr=v>>5, col nc=(v&31)*4

    float acc[4][8][4] = {};

    // prologue: stage 0
    #pragma unroll
    for (int pp = 0; pp < 8; pp++) {
        int v = tid + pp * 128;
        int m = v >> 3, kc = (v & 7) * 4;
        cpa16(smb + (m * APAD + kc) * 4, &A[(size_t)(bm + m) * K + kc]);
        int kr = v >> 5, nc = (v & 31) * 4;
        cpa16(smb + (A_WORDS + kr * BPAD + nc) * 4, &B[(size_t)kr * N + bn + nc]);
    }
    asm volatile("cp.async.commit_group;" ::: "memory");

    int buf = 0;
    for (int k0 = 0; k0 < K; k0 += 32) {
        const bool more = (k0 + 32 < K);
        if (more) {
            const uint32_t sb = smb + (buf ^ 1) * GEMM_BUF_WORDS * 4;
            #pragma unroll
            for (int pp = 0; pp < 8; pp++) {
                int v = tid + pp * 128;
                int m = v >> 3, kc = (v & 7) * 4;
                cpa16(sb + (m * APAD + kc) * 4,
                      &A[(size_t)(bm + m) * K + k0 + 32 + kc]);
                int kr = v >> 5, nc = (v & 31) * 4;
                cpa16(sb + (A_WORDS + kr * BPAD + nc) * 4,
                      &B[(size_t)(k0 + 32 + kr) * N + bn + nc]);
            }
            asm volatile("cp.async.commit_group;" ::: "memory");
            asm volatile("cp.async.wait_group 1;" ::: "memory");
        } else {
            asm volatile("cp.async.wait_group 0;" ::: "memory");
        }
        __syncthreads();

        const uint32_t* As = smU + buf * GEMM_BUF_WORDS;
        const uint32_t* Bs = As + A_WORDS;

        #pragma unroll
        for (int ks = 0; ks < 4; ks++) {
            const int ks8 = ks * 8;
            uint32_t af[4][4], bf[8][2];
            #pragma unroll
            for (int mi = 0; mi < 4; mi++) {
                int r = mW + mi * 16 + g;
                af[mi][0] = As[r * APAD + ks8 + t];
                af[mi][1] = As[(r + 8) * APAD + ks8 + t];
                af[mi][2] = As[r * APAD + ks8 + t + 4];
                af[mi][3] = As[(r + 8) * APAD + ks8 + t + 4];
            }
            #pragma unroll
            for (int ni = 0; ni < 8; ni++) {
                int c = nW + ni * 8 + g;
                bf[ni][0] = Bs[(ks8 + t) * BPAD + c];
                bf[ni][1] = Bs[(ks8 + t + 4) * BPAD + c];
            }
            #pragma unroll
            for (int mi = 0; mi < 4; mi++)
                #pragma unroll
                for (int ni = 0; ni < 8; ni++)
                    mma8(acc[mi][ni], af[mi], bf[ni]);
        }
        __syncthreads();
        buf ^= 1;
    }

    #pragma unroll
    for (int mi = 0; mi < 4; mi++)
        #pragma unroll
        for (int ni = 0; ni < 8; ni++) {
            int r = bm + mW + mi * 16 + g;
            int c = bn + nW + ni * 8 + 2 * t;
            *(float2*)&C[(size_t)r * N + c] =
                make_float2(acc[mi][ni][0], acc[mi][ni][1]);
            *(float2*)&C[(size_t)(r + 8) * N + c] =
                make_float2(acc[mi][ni][2], acc[mi][ni][3]);
        }
}

// ======================= fused flash cross-attention v2 ===================
#define KP  68
#define VP  72
#define CPW 132
#define FLASH_SMEM_WORDS (64 * KP + 64 * VP)   // 8960 words
#define QSC 0.18033688011112042f               // 0.125 * log2(e)

struct FA {
    const float* Q; const float* K; const float* V;
    float* Ct; int Nq; int Nk;
};

__global__ void __launch_bounds__(128, 2) flash2(FA a0, FA a1, int nbq0)
{
    __shared__ uint32_t sm[FLASH_SMEM_WORDS];
    uint32_t* Ks = sm;                  // 64 x KP
    uint32_t* Vs = sm + 64 * KP;        // 64 x VP

    const bool d1 = (blockIdx.x < nbq0);
    const FA a = d1 ? a0 : a1;
    const int bq = (d1 ? blockIdx.x : blockIdx.x - nbq0) * 128;
    const int h = blockIdx.y;
    const int Nq = a.Nq, Nk = a.Nk;
    const float* __restrict__ Qg = a.Q;
    const float* __restrict__ Kg = a.K;
    const float* __restrict__ Vg = a.V;

    const int tid = threadIdx.x;
    const int wid = tid >> 5, lane = tid & 31;
    const int g = lane >> 2, t = lane & 3;
    const int qw = wid * 32;

    #pragma unroll
    for (int pp = 0; pp < 16; pp++) {
        int idx = tid + pp * 128;
        int r = idx >> 4, c4 = (idx & 15) << 2;
        float4 q = *(const float4*)&Qg[(size_t)(bq + r) * DM + h * DKH + c4];
        uint4 u;
        u.x = f2t(q.x * QSC); u.y = f2t(q.y * QSC);
        u.z = f2t(q.z * QSC); u.w = f2t(q.w * QSC);
        *(uint4*)&sm[r * KP + c4] = u;
    }
    __syncthreads();

    uint32_t aq[2][8][4];
    #pragma unroll
    for (int grp = 0; grp < 2; grp++)
        #pragma unroll
        for (int ks = 0; ks < 8; ks++) {
            int r0 = qw + grp * 16 + g;
            aq[grp][ks][0] = sm[r0 * KP + ks * 8 + t];
            aq[grp][ks][1] = sm[(r0 + 8) * KP + ks * 8 + t];
            aq[grp][ks][2] = sm[r0 * KP + ks * 8 + t + 4];
            aq[grp][ks][3] = sm[(r0 + 8) * KP + ks * 8 + t + 4];
        }
    __syncthreads();

    float m[2][2], l[2][2];
    #pragma unroll
    for (int i = 0; i < 2; i++) { m[i][0] = m[i][1] = -1e30f; l[i][0] = l[i][1] = 0.f; }
    float o[2][8][4] = {};

    for (int kt = 0; kt < Nk; kt += 64) {
        #pragma unroll
        for (int pp = 0; pp < 8; pp++) {
            int idx = tid + pp * 128;
            int r = idx >> 4, c4 = (idx & 15) << 2;
            float4 kv = *(const float4*)&Kg[(size_t)(kt + r) * DM + h * DKH + c4];
            uint4 uk;
            uk.x = f2t(kv.x); uk.y = f2t(kv.y); uk.z = f2t(kv.z); uk.w = f2t(kv.w);
            *(uint4*)&Ks[r * KP + c4] = uk;
            float4 vv = *(const float4*)&Vg[(size_t)(kt + r) * DM + h * DKH + c4];
            int pr = (r & 0x38) | ((r & 7) >> 1) | ((r & 1) << 2);
            uint4 uv;
            uv.x = f2t(vv.x); uv.y = f2t(vv.y); uv.z = f2t(vv.z); uv.w = f2t(vv.w);
            *(uint4*)&Vs[pr * VP + c4] = uv;
        }
        __syncthreads();

        float s[2][8][4] = {};
        #pragma unroll
        for (int ni = 0; ni < 8; ni++) {
            #pragma unroll
            for (int ks = 0; ks < 8; ks++) {
                uint32_t bf[2];
                bf[0] = Ks[(ni * 8 + g) * KP + ks * 8 + t];
                bf[1] = Ks[(ni * 8 + g) * KP + ks * 8 + t + 4];
                mma8(s[0][ni], aq[0][ks], bf);
                mma8(s[1][ni], aq[1][ks], bf);
            }
        }

        #pragma unroll
        for (int grp = 0; grp < 2; grp++) {
            float mx0 = -1e30f, mx1 = -1e30f;
            #pragma unroll
            for (int ni = 0; ni < 8; ni++) {
                mx0 = fmaxf(mx0, fmaxf(s[grp][ni][0], s[grp][ni][1]));
                mx1 = fmaxf(mx1, fmaxf(s[grp][ni][2], s[grp][ni][3]));
            }
            #pragma unroll
            for (int off = 1; off <= 2; off <<= 1) {
                mx0 = fmaxf(mx0, __shfl_xor_sync(0xffffffffu, mx0, off));
                mx1 = fmaxf(mx1, __shfl_xor_sync(0xffffffffu, mx1, off));
            }
            float mn0 = fmaxf(m[grp][0], mx0), mn1 = fmaxf(m[grp][1], mx1);
            float cr0 = exp2f(m[grp][0] - mn0), cr1 = exp2f(m[grp][1] - mn1);
            m[grp][0] = mn0; m[grp][1] = mn1;

            float rs0 = 0.f, rs1 = 0.f;
            #pragma unroll
            for (int ni = 0; ni < 8; ni++) {
                s[grp][ni][0] = exp2f(s[grp][ni][0] - mn0);
                s[grp][ni][1] = exp2f(s[grp][ni][1] - mn0);
                s[grp][ni][2] = exp2f(s[grp][ni][2] - mn1);
                s[grp][ni][3] = exp2f(s[grp][ni][3] - mn1);
                rs0 += s[grp][ni][0] + s[grp][ni][1];
                rs1 += s[grp][ni][2] + s[grp][ni][3];
            }
            #pragma unroll
            for (int off = 1; off <= 2; off <<= 1) {
                rs0 += __shfl_xor_sync(0xffffffffu, rs0, off);
                rs1 += __shfl_xor_sync(0xffffffffu, rs1, off);
            }
            l[grp][0] = l[grp][0] * cr0 + rs0;
            l[grp][1] = l[grp][1] * cr1 + rs1;
            #pragma unroll
            for (int dn = 0; dn < 8; dn++) {
                o[grp][dn][0] *= cr0; o[grp][dn][1] *= cr0;
                o[grp][dn][2] *= cr1; o[grp][dn][3] *= cr1;
            }
        }

        #pragma unroll
        for (int kk = 0; kk < 8; kk++) {
            uint32_t ap0[4], ap1[4];
            ap0[0] = f2t(s[0][kk][0]); ap0[1] = f2t(s[0][kk][2]);
            ap0[2] = f2t(s[0][kk][1]); ap0[3] = f2t(s[0][kk][3]);
            ap1[0] = f2t(s[1][kk][0]); ap1[1] = f2t(s[1][kk][2]);
            ap1[2] = f2t(s[1][kk][1]); ap1[3] = f2t(s[1][kk][3]);
            #pragma unroll
            for (int dn = 0; dn < 8; dn++) {
                uint32_t bf[2];
                bf[0] = Vs[(kk * 8 + t) * VP + dn * 8 + g];
                bf[1] = Vs[(kk * 8 + t + 4) * VP + dn * 8 + g];
                mma8(o[0][dn], ap0, bf);
                mma8(o[1][dn], ap1, bf);
            }
        }
        __syncthreads();
    }

    // epilogue: normalize, tf32-round, transpose via smem, coalesced store
    float* Cs = (float*)sm;             // 64 x CPW
    #pragma unroll
    for (int grp = 0; grp < 2; grp++) {
        float i0 = 1.0f / l[grp][0], i1 = 1.0f / l[grp][1];
        int q = qw + grp * 16 + g;
        #pragma unroll
        for (int dn = 0; dn < 8; dn++) {
            int d = dn * 8 + 2 * t;
            Cs[d * CPW + q]           = __uint_as_float(f2t(o[grp][dn][0] * i0));
            Cs[(d + 1) * CPW + q]     = __uint_as_float(f2t(o[grp][dn][1] * i0));
            Cs[d * CPW + q + 8]       = __uint_as_float(f2t(o[grp][dn][2] * i1));
            Cs[(d + 1) * CPW + q + 8] = __uint_as_float(f2t(o[grp][dn][3] * i1));
        }
    }
    __syncthreads();

    float* Ct = a.Ct;
    #pragma unroll
    for (int pp = 0; pp < 16; pp++) {
        int idx = tid + pp * 128;
        int d = idx >> 5, q4 = (idx & 31) * 4;
        *(float4*)&Ct[(size_t)(h * DKH + d) * Nq + bq + q4] = *(float4*)&Cs[d * CPW + q4];
    }
}

// --------------------------------- launch ---------------------------------
extern "C" void kernel_launch(void* const* d_in, const int* in_sizes, int n_in,
                              void* d_out, int out_size)
{
    const float* X    = (const float*)d_in[0];
    const float* X1   = (const float*)d_in[1];
    const float* WQ   = (const float*)d_in[2];
    const float* WK   = (const float*)d_in[3];
    const float* WV   = (const float*)d_in[4];
    const float* WQ1  = (const float*)d_in[5];
    const float* WK1  = (const float*)d_in[6];
    const float* WV1  = (const float*)d_in[7];
    const float* Wfc  = (const float*)d_in[8];
    const float* Wfc1 = (const float*)d_in[9];
    float* out = (float*)d_out;

    float *Q, *K, *V, *Q1, *K1, *V1, *C, *C1, *cvb;
    cudaGetSymbolAddress((void**)&Q,  g_Q);
    cudaGetSymbolAddress((void**)&K,  g_K);
    cudaGetSymbolAddress((void**)&V,  g_V);
    cudaGetSymbolAddress((void**)&Q1, g_Q1);
    cudaGetSymbolAddress((void**)&K1, g_K1);
    cudaGetSymbolAddress((void**)&V1, g_V1);
    cudaGetSymbolAddress((void**)&C,  g_C);
    cudaGetSymbolAddress((void**)&C1, g_C1);
    cudaGetSymbolAddress((void**)&cvb, g_cv);

    // tf32-rounded copies
    float* Xc    = cvb;
    float* X1c   = cvb + (size_t)2 * MEG;
    float* WQc   = cvb + (size_t)5 * MEG;
    float* WKc   = cvb + (size_t)6 * MEG;
    float* WVc   = cvb + (size_t)7 * MEG;
    float* WQ1c  = cvb + (size_t)8 * MEG;
    float* WK1c  = cvb + (size_t)9 * MEG;
    float* WV1c  = cvb + (size_t)10 * MEG;
    float* Wfcc  = cvb + (size_t)11 * MEG;
    float* Wfc1c = cvb + (size_t)12 * MEG;

    static bool attr_done = false;
    if (!attr_done) {
        cudaFuncSetAttribute(gemmN_tf32,
            cudaFuncAttributeMaxDynamicSharedMemorySize, GEMM_SMEM_BYTES);
        attr_done = true;
    }

    // pre-pass: round inputs to tf32-valued fp32
    {
        CV cv;
        const float* srcs[10] = {X, X1, WQ, WK, WV, WQ1, WK1, WV1, Wfc, Wfc1};
        float* dsts[10] = {Xc, X1c, WQc, WKc, WVc, WQ1c, WK1c, WV1c, Wfcc, Wfc1c};
        int sz[10] = {N0 * DM, NN1 * DM, MEG, MEG, MEG, MEG, MEG, MEG, MEG, MEG};
        for (int i = 0; i < 10; i++) {
            cv.src[i] = (const float4*)srcs[i];
            cv.dst[i] = (float4*)dsts[i];
            cv.n4[i] = sz[i] / 4;
        }
        cvt_tf32<<<dim3(296, 1, 10), 256>>>(cv);
    }

    // ALL SIX QKV projections in one launch (z selects GEMM)
    {
        GN p;
        p.A[0] = Xc;   p.A[1] = Xc;   p.A[2] = Xc;
        p.A[3] = X1c;  p.A[4] = X1c;  p.A[5] = X1c;
        p.B[0] = WQc;  p.B[1] = WKc;  p.B[2] = WVc;
        p.B[3] = WQ1c; p.B[4] = WK1c; p.B[5] = WV1c;
        p.C[0] = Q;    p.C[1] = K;    p.C[2] = V;
        p.C[3] = Q1;   p.C[4] = K1;   p.C[5] = V1;
        p.M[0] = N0;   p.M[1] = N0;   p.M[2] = N0;
        p.M[3] = NN1;  p.M[4] = NN1;  p.M[5] = NN1;
        gemmN_tf32<<<dim3(DM / 128, NN1 / 128, 6), dim3(128), GEMM_SMEM_BYTES>>>(p, DM, DM);
    }

    // fused attention: both directions in ONE launch
    {
        FA a0, a1;
        a0.Q = Q1; a0.K = K;  a0.V = V;  a0.Ct = C;  a0.Nq = NN1; a0.Nk = N0;
        a1.Q = Q;  a1.K = K1; a1.V = V1; a1.Ct = C1; a1.Nq = N0;  a1.Nk = NN1;
        const int nbq0 = NN1 / 128;                  // 24
        const int nbq1 = N0 / 128;                   // 16
        flash2<<<dim3(nbq0 + nbq1, NH), dim3(128)>>>(a0, a1, nbq0);
    }

    // final FCs in one launch (C/C1 already tf32-valued from flash epilogue)
    {
        GN p;
        p.A[0] = C;    p.A[1] = C1;
        p.B[0] = Wfcc; p.B[1] = Wfc1c;
        p.C[0] = out;  p.C[1] = out + (size_t)NN1 * DM;
        p.M[0] = NN1;  p.M[1] = N0;
        p.A[2] = p.A[3] = p.A[4] = p.A[5] = C;
        p.B[2] = p.B[3] = p.B[4] = p.B[5] = Wfcc;
        p.C[2] = p.C[3] = p.C[4] = p.C[5] = out;
        p.M[2] = p.M[3] = p.M[4] = p.M[5] = 0;
        gemmN_tf32<<<dim3(DM / 128, NN1 / 128, 2), dim3(128), GEMM_SMEM_BYTES>>>(p, DM, DM);
    }
}